// round 1
// baseline (speedup 1.0000x reference)
#include <cuda_runtime.h>
#include <math.h>

#define Bx     256
#define Tx     128
#define ENCX   1024
#define UX     1024
#define EMBX   512
#define VOCABX 32000
#define XDIM   1536   // ENC + EMBED
#define WXN    3072   // 3*U
#define GXN    2048   // virtual cols: [z | hh] (r is dead in the reference)

// ---------------- scratch (allocation-free: __device__ globals) ----------------
__device__ float g_hw2[Bx * UX];     // hidden@W2 + b1 + b2
__device__ float g_S[Bx * Tx];       // attention scores (pre-softmax, sans bv)
__device__ float g_xt[Bx * XDIM];    // [context | emb]
__device__ float g_gx[Bx * GXN];     // [gx_z | gx_hh]

// ---------------- zero S ----------------
__global__ void k_zero_S() {
    int i = blockIdx.x * blockDim.x + threadIdx.x;
    if (i < Bx * Tx) g_S[i] = 0.f;
}

// ---------------- hw2 = hidden @ W2 + (b1 + b2) ----------------
// 64x64x16 tiles, 256 threads, 4x4 microtile. grid (UX/64, Bx/64) = (16,4)
__global__ void k_hw2(const float* __restrict__ hidden, const float* __restrict__ W2,
                      const float* __restrict__ b1, const float* __restrict__ b2) {
    __shared__ float As[16][64];
    __shared__ float Bs[16][64];
    int tid = threadIdx.x;
    int m0 = blockIdx.y * 64, n0 = blockIdx.x * 64;
    int ar = tid >> 2, ac = (tid & 3) << 2;
    int br = tid >> 4, bc = (tid & 15) << 2;
    int ty = tid >> 4, tx = tid & 15;
    float acc[4][4] = {};
    for (int k0 = 0; k0 < UX; k0 += 16) {
        float4 av = *(const float4*)&hidden[(size_t)(m0 + ar) * UX + k0 + ac];
        float4 bv = *(const float4*)&W2[(size_t)(k0 + br) * UX + n0 + bc];
        __syncthreads();
        As[ac + 0][ar] = av.x; As[ac + 1][ar] = av.y;
        As[ac + 2][ar] = av.z; As[ac + 3][ar] = av.w;
        *(float4*)&Bs[br][bc] = bv;
        __syncthreads();
#pragma unroll
        for (int k = 0; k < 16; k++) {
            float ra[4], rb[4];
#pragma unroll
            for (int i = 0; i < 4; i++) ra[i] = As[k][ty * 4 + i];
#pragma unroll
            for (int j = 0; j < 4; j++) rb[j] = Bs[k][tx * 4 + j];
#pragma unroll
            for (int i = 0; i < 4; i++)
#pragma unroll
                for (int j = 0; j < 4; j++) acc[i][j] += ra[i] * rb[j];
        }
    }
#pragma unroll
    for (int i = 0; i < 4; i++) {
        int m = m0 + ty * 4 + i;
#pragma unroll
        for (int j = 0; j < 4; j++) {
            int n = n0 + tx * 4 + j;
            g_hw2[(size_t)m * UX + n] = acc[i][j] + b1[n] + b2[n];
        }
    }
}

// ---------------- S[b,t] += sum_u tanh(enc@W1 + hw2)[b,t,u] * V[u] ----------------
// Big fused GEMM: M = B*T = 32768, N = U = 1024, K = ENC = 1024.
// BM=128 aligns exactly with one batch element (T=128). 128x128x8 tiles,
// 256 threads, 8x8 microtile, fused tanh*V reduce epilogue + row atomicAdd.
// grid (UX/128, Bx) = (8, 256)
__global__ void k_score(const float* __restrict__ enc, const float* __restrict__ W1,
                        const float* __restrict__ V) {
    __shared__ float As[8][128];
    __shared__ float Bs[8][128];
    __shared__ float hw2s[128];
    __shared__ float Vs[128];
    __shared__ float red[128][17];
    int tid = threadIdx.x;
    int b = blockIdx.y;
    int n0 = blockIdx.x * 128;
    if (tid < 128) {
        hw2s[tid] = g_hw2[(size_t)b * UX + n0 + tid];
        Vs[tid] = V[n0 + tid];
    }
    int ar = tid >> 1, ac = (tid & 1) << 2;
    int br = tid >> 5, bc = (tid & 31) << 2;
    int ty = tid >> 4, tx = tid & 15;
    float acc[8][8] = {};
    const float* Arow = enc + (size_t)(b * Tx + ar) * ENCX;
    for (int k0 = 0; k0 < ENCX; k0 += 8) {
        float4 av = *(const float4*)&Arow[k0 + ac];
        float4 bv = *(const float4*)&W1[(size_t)(k0 + br) * UX + n0 + bc];
        __syncthreads();
        As[ac + 0][ar] = av.x; As[ac + 1][ar] = av.y;
        As[ac + 2][ar] = av.z; As[ac + 3][ar] = av.w;
        *(float4*)&Bs[br][bc] = bv;
        __syncthreads();
#pragma unroll
        for (int k = 0; k < 8; k++) {
            float ra[8], rb[8];
#pragma unroll
            for (int i = 0; i < 8; i++) ra[i] = As[k][ty * 8 + i];
#pragma unroll
            for (int j = 0; j < 8; j++) rb[j] = Bs[k][tx * 8 + j];
#pragma unroll
            for (int i = 0; i < 8; i++)
#pragma unroll
                for (int j = 0; j < 8; j++) acc[i][j] += ra[i] * rb[j];
        }
    }
    __syncthreads();
#pragma unroll
    for (int i = 0; i < 8; i++) {
        float p = 0.f;
#pragma unroll
        for (int j = 0; j < 8; j++)
            p += tanhf(acc[i][j] + hw2s[tx * 8 + j]) * Vs[tx * 8 + j];
        red[ty * 8 + i][tx] = p;
    }
    __syncthreads();
    if (tid < 128) {
        float s = 0.f;
#pragma unroll
        for (int x2 = 0; x2 < 16; x2++) s += red[tid][x2];
        atomicAdd(&g_S[b * Tx + tid], s);
    }
}

// ---------------- softmax over T, context, emb gather ----------------
// grid = B, 128 threads. bv dropped: softmax is shift-invariant.
__global__ void k_softmax_ctx(const float* __restrict__ enc, const float* __restrict__ E,
                              const int* __restrict__ x, float* __restrict__ attn_out) {
    int b = blockIdx.x;
    int tid = threadIdx.x;
    __shared__ float sh[128];
    __shared__ float attn_sh[128];
    float s = g_S[b * Tx + tid];
    sh[tid] = s;
    __syncthreads();
    for (int off = 64; off; off >>= 1) {
        if (tid < off) sh[tid] = fmaxf(sh[tid], sh[tid + off]);
        __syncthreads();
    }
    float mx = sh[0];
    __syncthreads();
    float e = expf(s - mx);
    sh[tid] = e;
    __syncthreads();
    for (int off = 64; off; off >>= 1) {
        if (tid < off) sh[tid] = sh[tid] + sh[tid + off];
        __syncthreads();
    }
    float a = e / sh[0];
    attn_sh[tid] = a;
    attn_out[b * Tx + tid] = a;
    __syncthreads();
    // context[b, e] = sum_t attn[t] * enc[b, t, e]
    for (int ec = tid; ec < ENCX; ec += 128) {
        float c = 0.f;
        const float* p = enc + (size_t)b * Tx * ENCX + ec;
#pragma unroll 8
        for (int t = 0; t < Tx; t++) c += attn_sh[t] * p[(size_t)t * ENCX];
        g_xt[(size_t)b * XDIM + ec] = c;
    }
    // emb gather
    int row = x[b];
    for (int e2 = tid; e2 < EMBX; e2 += 128)
        g_xt[(size_t)b * XDIM + ENCX + e2] = E[(size_t)row * EMBX + e2];
}

// ---------------- gates: gx_z, gx_hh = xt @ Wx[:, {z, hh}] + b_gru ----------------
// virtual N = 2048 (skip dead r columns). 64x64x16 tiles. grid (32, 4)
__global__ void k_gate(const float* __restrict__ Wx, const float* __restrict__ bg) {
    __shared__ float As[16][64];
    __shared__ float Bs[16][64];
    int tid = threadIdx.x;
    int m0 = blockIdx.y * 64;
    int nv0 = blockIdx.x * 64;
    int na0 = (nv0 < UX) ? nv0 : nv0 + UX;  // map hh half to Wx cols [2U, 3U)
    int ar = tid >> 2, ac = (tid & 3) << 2;
    int br = tid >> 4, bc = (tid & 15) << 2;
    int ty = tid >> 4, tx = tid & 15;
    float acc[4][4] = {};
    for (int k0 = 0; k0 < XDIM; k0 += 16) {
        float4 av = *(const float4*)&g_xt[(size_t)(m0 + ar) * XDIM + k0 + ac];
        float4 bv = *(const float4*)&Wx[(size_t)(k0 + br) * WXN + na0 + bc];
        __syncthreads();
        As[ac + 0][ar] = av.x; As[ac + 1][ar] = av.y;
        As[ac + 2][ar] = av.z; As[ac + 3][ar] = av.w;
        *(float4*)&Bs[br][bc] = bv;
        __syncthreads();
#pragma unroll
        for (int k = 0; k < 16; k++) {
            float ra[4], rb[4];
#pragma unroll
            for (int i = 0; i < 4; i++) ra[i] = As[k][ty * 4 + i];
#pragma unroll
            for (int j = 0; j < 4; j++) rb[j] = Bs[k][tx * 4 + j];
#pragma unroll
            for (int i = 0; i < 4; i++)
#pragma unroll
                for (int j = 0; j < 4; j++) acc[i][j] += ra[i] * rb[j];
        }
    }
#pragma unroll
    for (int i = 0; i < 4; i++) {
        int m = m0 + ty * 4 + i;
#pragma unroll
        for (int j = 0; j < 4; j++) {
            int nv = nv0 + tx * 4 + j;
            int na = na0 + tx * 4 + j;
            g_gx[(size_t)m * GXN + nv] = acc[i][j] + bg[na];
        }
    }
}

// ---------------- state = (1 - sigmoid(gz)) * tanh(ghh) ----------------
__global__ void k_state(float* __restrict__ out_state) {
    int i = blockIdx.x * blockDim.x + threadIdx.x;
    if (i >= Bx * UX) return;
    int bb = i >> 10, u = i & 1023;
    float gz = g_gx[(size_t)bb * GXN + u];
    float gh = g_gx[(size_t)bb * GXN + UX + u];
    float z = 1.f / (1.f + expf(-gz));
    out_state[i] = (1.f - z) * tanhf(gh);
}

// ---------------- logits = state @ Wfc + bfc ----------------
// M=256, N=32000, K=1024. 128x128x8 tiles. grid (250, 2)
__global__ void k_logits(const float* __restrict__ A, const float* __restrict__ Wfc,
                         const float* __restrict__ bfc, float* __restrict__ C) {
    __shared__ float As[8][128];
    __shared__ float Bs[8][128];
    int tid = threadIdx.x;
    int m0 = blockIdx.y * 128, n0 = blockIdx.x * 128;
    int ar = tid >> 1, ac = (tid & 1) << 2;
    int br = tid >> 5, bc = (tid & 31) << 2;
    int ty = tid >> 4, tx = tid & 15;
    float acc[8][8] = {};
    for (int k0 = 0; k0 < UX; k0 += 8) {
        float4 av = *(const float4*)&A[(size_t)(m0 + ar) * UX + k0 + ac];
        float4 bv = *(const float4*)&Wfc[(size_t)(k0 + br) * VOCABX + n0 + bc];
        __syncthreads();
        As[ac + 0][ar] = av.x; As[ac + 1][ar] = av.y;
        As[ac + 2][ar] = av.z; As[ac + 3][ar] = av.w;
        *(float4*)&Bs[br][bc] = bv;
        __syncthreads();
#pragma unroll
        for (int k = 0; k < 8; k++) {
            float ra[8], rb[8];
#pragma unroll
            for (int i = 0; i < 8; i++) ra[i] = As[k][ty * 8 + i];
#pragma unroll
            for (int j = 0; j < 8; j++) rb[j] = Bs[k][tx * 8 + j];
#pragma unroll
            for (int i = 0; i < 8; i++)
#pragma unroll
                for (int j = 0; j < 8; j++) acc[i][j] += ra[i] * rb[j];
        }
    }
#pragma unroll
    for (int i = 0; i < 8; i++) {
        int m = m0 + ty * 8 + i;
#pragma unroll
        for (int j = 0; j < 8; j++) {
            int n = n0 + tx * 8 + j;
            C[(size_t)m * VOCABX + n] = acc[i][j] + bfc[n];
        }
    }
}

// ---------------- launcher ----------------
extern "C" void kernel_launch(void* const* d_in, const int* in_sizes, int n_in,
                              void* d_out, int out_size) {
    const int*   x      = (const int*)d_in[0];
    const float* hidden = (const float*)d_in[1];
    const float* enc    = (const float*)d_in[2];
    const float* E      = (const float*)d_in[3];
    const float* W1     = (const float*)d_in[4];
    const float* b1     = (const float*)d_in[5];
    const float* W2     = (const float*)d_in[6];
    const float* b2     = (const float*)d_in[7];
    const float* V      = (const float*)d_in[8];
    // d_in[9]  = bv     (dropped: softmax shift-invariant, score not an output)
    const float* Wx     = (const float*)d_in[10];
    // d_in[11] = Wh     (dead in reference)
    const float* b_gru  = (const float*)d_in[12];
    const float* Wfc    = (const float*)d_in[13];
    const float* bfc    = (const float*)d_in[14];

    float* out        = (float*)d_out;
    float* out_logits = out;                                  // B*VOCAB
    float* out_state  = out + (size_t)Bx * VOCABX;            // B*U
    float* out_attn   = out + (size_t)Bx * VOCABX + Bx * UX;  // B*T

    k_zero_S<<<(Bx * Tx + 255) / 256, 256>>>();
    k_hw2<<<dim3(UX / 64, Bx / 64), 256>>>(hidden, W2, b1, b2);
    k_score<<<dim3(UX / 128, Bx), 256>>>(enc, W1, V);
    k_softmax_ctx<<<Bx, 128>>>(enc, E, x, out_attn);
    k_gate<<<dim3(GXN / 64, Bx / 64), 256>>>(Wx, b_gru);
    k_state<<<(Bx * UX + 255) / 256, 256>>>(out_state);
    k_logits<<<dim3(VOCABX / 128, Bx / 128), 256>>>(out_state, Wfc, bfc, out_logits);
}

// round 2
// speedup vs baseline: 2.3297x; 2.3297x over previous
#include <cuda_runtime.h>
#include <math.h>

#define Bx     256
#define Tx     128
#define ENCX   1024
#define UX     1024
#define EMBX   512
#define VOCABX 32000
#define XDIM   1536   // ENC + EMBED
#define WXN    3072   // 3*U
#define GXN    2048   // virtual cols: [z | hh] (r is dead in the reference)
#define SMSTRIDE 136  // 128 + 8 pad -> conflict-free tf32 fragment LDS

// ---------------- scratch (allocation-free: __device__ globals) ----------------
__device__ float g_hw2[Bx * UX];     // hidden@W2 + b1 + b2
__device__ float g_S[Bx * Tx];       // attention scores (pre-softmax, sans bv)
__device__ float g_attn[Bx * Tx];    // softmax(S)
__device__ float g_xt[Bx * XDIM];    // [context | emb]
__device__ float g_gx[Bx * GXN];     // [gx_z | gx_hh]

__device__ __forceinline__ float f2tf(float f) {
    unsigned u;
    asm("cvt.rna.tf32.f32 %0, %1;" : "=r"(u) : "f"(f));
    return __uint_as_float(u);
}

__device__ __forceinline__ void mma_tf32(float* c, const unsigned* a, const unsigned* b) {
    asm volatile(
        "mma.sync.aligned.m16n8k8.row.col.f32.tf32.tf32.f32 "
        "{%0,%1,%2,%3}, {%4,%5,%6,%7}, {%8,%9}, {%0,%1,%2,%3};"
        : "+f"(c[0]), "+f"(c[1]), "+f"(c[2]), "+f"(c[3])
        : "r"(a[0]), "r"(a[1]), "r"(a[2]), "r"(a[3]), "r"(b[0]), "r"(b[1]));
}

// ---------------- zero S ----------------
__global__ void k_zero_S() {
    int i = blockIdx.x * blockDim.x + threadIdx.x;
    if (i < Bx * Tx) g_S[i] = 0.f;
}

// ---------------- hw2 = hidden @ W2 + (b1 + b2) ----------------
__global__ void k_hw2(const float* __restrict__ hidden, const float* __restrict__ W2,
                      const float* __restrict__ b1, const float* __restrict__ b2) {
    __shared__ float As[16][64];
    __shared__ float Bs[16][64];
    int tid = threadIdx.x;
    int m0 = blockIdx.y * 64, n0 = blockIdx.x * 64;
    int ar = tid >> 2, ac = (tid & 3) << 2;
    int br = tid >> 4, bc = (tid & 15) << 2;
    int ty = tid >> 4, tx = tid & 15;
    float acc[4][4] = {};
    for (int k0 = 0; k0 < UX; k0 += 16) {
        float4 av = *(const float4*)&hidden[(size_t)(m0 + ar) * UX + k0 + ac];
        float4 bv = *(const float4*)&W2[(size_t)(k0 + br) * UX + n0 + bc];
        __syncthreads();
        As[ac + 0][ar] = av.x; As[ac + 1][ar] = av.y;
        As[ac + 2][ar] = av.z; As[ac + 3][ar] = av.w;
        *(float4*)&Bs[br][bc] = bv;
        __syncthreads();
#pragma unroll
        for (int k = 0; k < 16; k++) {
            float ra[4], rb[4];
#pragma unroll
            for (int i = 0; i < 4; i++) ra[i] = As[k][ty * 4 + i];
#pragma unroll
            for (int j = 0; j < 4; j++) rb[j] = Bs[k][tx * 4 + j];
#pragma unroll
            for (int i = 0; i < 4; i++)
#pragma unroll
                for (int j = 0; j < 4; j++) acc[i][j] += ra[i] * rb[j];
        }
    }
#pragma unroll
    for (int i = 0; i < 4; i++) {
        int m = m0 + ty * 4 + i;
#pragma unroll
        for (int j = 0; j < 4; j++) {
            int n = n0 + tx * 4 + j;
            g_hw2[(size_t)m * UX + n] = acc[i][j] + b1[n] + b2[n];
        }
    }
}

// ---------------- score GEMM on tensor cores (tf32 mma.sync) ----------------
// M = B*T (BM=128 == one batch element), N = U, K = ENC.
// BM=128, BN=128, BK=16; 8 warps in 2(m) x 4(n); warptile 64x32; m16n8k8.
// Fused epilogue: S[b,t] += sum_n tanh(acc + hw2[n]) * V[n]. grid (8, 256)
__global__ void __launch_bounds__(256, 2)
k_score_tc(const float* __restrict__ enc, const float* __restrict__ W1,
           const float* __restrict__ V) {
    __shared__ float As[16][SMSTRIDE];
    __shared__ float Bs[16][SMSTRIDE];
    __shared__ float hw2s[128];
    __shared__ float Vs[128];
    __shared__ float red[128][5];
    int tid = threadIdx.x;
    int lane = tid & 31, wid = tid >> 5;
    int warp_m = wid & 1, warp_n = wid >> 1;
    int g = lane >> 2, tig = lane & 3;
    int b = blockIdx.y;
    int n0 = blockIdx.x * 128;

    if (tid < 128) {
        hw2s[tid] = g_hw2[(size_t)b * UX + n0 + tid];
        Vs[tid] = V[n0 + tid];
    }

    int am = tid >> 1, akc = (tid & 1) * 8;
    int bk = tid >> 4, bnc = (tid & 15) * 8;
    const float* Ap = enc + (size_t)(b * Tx + am) * ENCX + akc;
    const float* Bp = W1 + (size_t)bk * UX + n0 + bnc;

    float acc[4][4][4] = {};

    for (int k0 = 0; k0 < ENCX; k0 += 16) {
        float4 av0 = *(const float4*)(Ap + k0);
        float4 av1 = *(const float4*)(Ap + k0 + 4);
        float4 bv0 = *(const float4*)(Bp + (size_t)k0 * UX);
        float4 bv1 = *(const float4*)(Bp + (size_t)k0 * UX + 4);
        __syncthreads();
        As[akc + 0][am] = f2tf(av0.x); As[akc + 1][am] = f2tf(av0.y);
        As[akc + 2][am] = f2tf(av0.z); As[akc + 3][am] = f2tf(av0.w);
        As[akc + 4][am] = f2tf(av1.x); As[akc + 5][am] = f2tf(av1.y);
        As[akc + 6][am] = f2tf(av1.z); As[akc + 7][am] = f2tf(av1.w);
        Bs[bk][bnc + 0] = f2tf(bv0.x); Bs[bk][bnc + 1] = f2tf(bv0.y);
        Bs[bk][bnc + 2] = f2tf(bv0.z); Bs[bk][bnc + 3] = f2tf(bv0.w);
        Bs[bk][bnc + 4] = f2tf(bv1.x); Bs[bk][bnc + 5] = f2tf(bv1.y);
        Bs[bk][bnc + 6] = f2tf(bv1.z); Bs[bk][bnc + 7] = f2tf(bv1.w);
        __syncthreads();
#pragma unroll
        for (int kk = 0; kk < 16; kk += 8) {
            unsigned afr[4][4], bfr[4][2];
#pragma unroll
            for (int i = 0; i < 4; i++) {
                int row = warp_m * 64 + i * 16 + g;
                afr[i][0] = __float_as_uint(As[kk + tig][row]);
                afr[i][1] = __float_as_uint(As[kk + tig][row + 8]);
                afr[i][2] = __float_as_uint(As[kk + tig + 4][row]);
                afr[i][3] = __float_as_uint(As[kk + tig + 4][row + 8]);
            }
#pragma unroll
            for (int j = 0; j < 4; j++) {
                int col = warp_n * 32 + j * 8 + g;
                bfr[j][0] = __float_as_uint(Bs[kk + tig][col]);
                bfr[j][1] = __float_as_uint(Bs[kk + tig + 4][col]);
            }
#pragma unroll
            for (int i = 0; i < 4; i++)
#pragma unroll
                for (int j = 0; j < 4; j++) mma_tf32(acc[i][j], afr[i], bfr[j]);
        }
    }

    // epilogue: per-row sum of tanh(acc + hw2)*V
#pragma unroll
    for (int i = 0; i < 4; i++) {
        float s0 = 0.f, s1 = 0.f;
#pragma unroll
        for (int j = 0; j < 4; j++) {
            int nb = warp_n * 32 + j * 8 + tig * 2;
#pragma unroll
            for (int c = 0; c < 2; c++) {
                int n = nb + c;
                s0 += tanhf(acc[i][j][c] + hw2s[n]) * Vs[n];
                s1 += tanhf(acc[i][j][2 + c] + hw2s[n]) * Vs[n];
            }
        }
        s0 += __shfl_xor_sync(0xffffffffu, s0, 1);
        s0 += __shfl_xor_sync(0xffffffffu, s0, 2);
        s1 += __shfl_xor_sync(0xffffffffu, s1, 1);
        s1 += __shfl_xor_sync(0xffffffffu, s1, 2);
        if (tig == 0) {
            int r0 = warp_m * 64 + i * 16 + g;
            red[r0][warp_n] = s0;
            red[r0 + 8][warp_n] = s1;
        }
    }
    __syncthreads();
    if (tid < 128) {
        float s = red[tid][0] + red[tid][1] + red[tid][2] + red[tid][3];
        atomicAdd(&g_S[b * Tx + tid], s);
    }
}

// ---------------- softmax over T + emb gather ----------------
__global__ void k_softmax(const int* __restrict__ x, const float* __restrict__ E,
                          float* __restrict__ attn_out) {
    int b = blockIdx.x;
    int tid = threadIdx.x;
    __shared__ float sh[128];
    float s = g_S[b * Tx + tid];
    sh[tid] = s;
    __syncthreads();
    for (int off = 64; off; off >>= 1) {
        if (tid < off) sh[tid] = fmaxf(sh[tid], sh[tid + off]);
        __syncthreads();
    }
    float mx = sh[0];
    __syncthreads();
    float e = expf(s - mx);
    sh[tid] = e;
    __syncthreads();
    for (int off = 64; off; off >>= 1) {
        if (tid < off) sh[tid] = sh[tid] + sh[tid + off];
        __syncthreads();
    }
    float a = e / sh[0];
    g_attn[b * Tx + tid] = a;
    attn_out[b * Tx + tid] = a;
    // emb gather
    int row = x[b];
    for (int e2 = tid; e2 < EMBX; e2 += 128)
        g_xt[(size_t)b * XDIM + ENCX + e2] = E[(size_t)row * EMBX + e2];
}

// ---------------- context: g_xt[b, :ENC] = attn[b] . enc[b] ----------------
// grid (B, ENC/256), 256 threads: one output column per thread, coalesced enc reads
__global__ void k_ctx(const float* __restrict__ enc) {
    int b = blockIdx.x;
    int ec = blockIdx.y * 256 + threadIdx.x;
    __shared__ float attn_sh[128];
    if (threadIdx.x < 128) attn_sh[threadIdx.x] = g_attn[b * Tx + threadIdx.x];
    __syncthreads();
    const float* p = enc + (size_t)b * Tx * ENCX + ec;
    float c = 0.f;
#pragma unroll 8
    for (int t = 0; t < Tx; t++) c += attn_sh[t] * p[(size_t)t * ENCX];
    g_xt[(size_t)b * XDIM + ec] = c;
}

// ---------------- gates: gx_z, gx_hh = xt @ Wx[:, {z, hh}] + b_gru ----------------
__global__ void k_gate(const float* __restrict__ Wx, const float* __restrict__ bg) {
    __shared__ float As[16][64];
    __shared__ float Bs[16][64];
    int tid = threadIdx.x;
    int m0 = blockIdx.y * 64;
    int nv0 = blockIdx.x * 64;
    int na0 = (nv0 < UX) ? nv0 : nv0 + UX;
    int ar = tid >> 2, ac = (tid & 3) << 2;
    int br = tid >> 4, bc = (tid & 15) << 2;
    int ty = tid >> 4, tx = tid & 15;
    float acc[4][4] = {};
    for (int k0 = 0; k0 < XDIM; k0 += 16) {
        float4 av = *(const float4*)&g_xt[(size_t)(m0 + ar) * XDIM + k0 + ac];
        float4 bv = *(const float4*)&Wx[(size_t)(k0 + br) * WXN + na0 + bc];
        __syncthreads();
        As[ac + 0][ar] = av.x; As[ac + 1][ar] = av.y;
        As[ac + 2][ar] = av.z; As[ac + 3][ar] = av.w;
        *(float4*)&Bs[br][bc] = bv;
        __syncthreads();
#pragma unroll
        for (int k = 0; k < 16; k++) {
            float ra[4], rb[4];
#pragma unroll
            for (int i = 0; i < 4; i++) ra[i] = As[k][ty * 4 + i];
#pragma unroll
            for (int j = 0; j < 4; j++) rb[j] = Bs[k][tx * 4 + j];
#pragma unroll
            for (int i = 0; i < 4; i++)
#pragma unroll
                for (int j = 0; j < 4; j++) acc[i][j] += ra[i] * rb[j];
        }
    }
#pragma unroll
    for (int i = 0; i < 4; i++) {
        int m = m0 + ty * 4 + i;
#pragma unroll
        for (int j = 0; j < 4; j++) {
            int nv = nv0 + tx * 4 + j;
            int na = na0 + tx * 4 + j;
            g_gx[(size_t)m * GXN + nv] = acc[i][j] + bg[na];
        }
    }
}

// ---------------- state = (1 - sigmoid(gz)) * tanh(ghh) ----------------
__global__ void k_state(float* __restrict__ out_state) {
    int i = blockIdx.x * blockDim.x + threadIdx.x;
    if (i >= Bx * UX) return;
    int bb = i >> 10, u = i & 1023;
    float gz = g_gx[(size_t)bb * GXN + u];
    float gh = g_gx[(size_t)bb * GXN + UX + u];
    float z = 1.f / (1.f + expf(-gz));
    out_state[i] = (1.f - z) * tanhf(gh);
}

// ---------------- logits GEMM on tensor cores (tf32 mma.sync) ----------------
// M=256, N=32000, K=1024. BM=128, BN=128, BK=16. grid (250, 2)
__global__ void __launch_bounds__(256, 2)
k_logits_tc(const float* __restrict__ A, const float* __restrict__ Wfc,
            const float* __restrict__ bfc, float* __restrict__ C) {
    __shared__ float As[16][SMSTRIDE];
    __shared__ float Bs[16][SMSTRIDE];
    int tid = threadIdx.x;
    int lane = tid & 31, wid = tid >> 5;
    int warp_m = wid & 1, warp_n = wid >> 1;
    int g = lane >> 2, tig = lane & 3;
    int m0 = blockIdx.y * 128, n0 = blockIdx.x * 128;

    int am = tid >> 1, akc = (tid & 1) * 8;
    int bk = tid >> 4, bnc = (tid & 15) * 8;
    const float* Ap = A + (size_t)(m0 + am) * UX + akc;
    const float* Bp = Wfc + (size_t)bk * VOCABX + n0 + bnc;

    float acc[4][4][4] = {};

    for (int k0 = 0; k0 < UX; k0 += 16) {
        float4 av0 = *(const float4*)(Ap + k0);
        float4 av1 = *(const float4*)(Ap + k0 + 4);
        float4 bv0 = *(const float4*)(Bp + (size_t)k0 * VOCABX);
        float4 bv1 = *(const float4*)(Bp + (size_t)k0 * VOCABX + 4);
        __syncthreads();
        As[akc + 0][am] = f2tf(av0.x); As[akc + 1][am] = f2tf(av0.y);
        As[akc + 2][am] = f2tf(av0.z); As[akc + 3][am] = f2tf(av0.w);
        As[akc + 4][am] = f2tf(av1.x); As[akc + 5][am] = f2tf(av1.y);
        As[akc + 6][am] = f2tf(av1.z); As[akc + 7][am] = f2tf(av1.w);
        Bs[bk][bnc + 0] = f2tf(bv0.x); Bs[bk][bnc + 1] = f2tf(bv0.y);
        Bs[bk][bnc + 2] = f2tf(bv0.z); Bs[bk][bnc + 3] = f2tf(bv0.w);
        Bs[bk][bnc + 4] = f2tf(bv1.x); Bs[bk][bnc + 5] = f2tf(bv1.y);
        Bs[bk][bnc + 6] = f2tf(bv1.z); Bs[bk][bnc + 7] = f2tf(bv1.w);
        __syncthreads();
#pragma unroll
        for (int kk = 0; kk < 16; kk += 8) {
            unsigned afr[4][4], bfr[4][2];
#pragma unroll
            for (int i = 0; i < 4; i++) {
                int row = warp_m * 64 + i * 16 + g;
                afr[i][0] = __float_as_uint(As[kk + tig][row]);
                afr[i][1] = __float_as_uint(As[kk + tig][row + 8]);
                afr[i][2] = __float_as_uint(As[kk + tig + 4][row]);
                afr[i][3] = __float_as_uint(As[kk + tig + 4][row + 8]);
            }
#pragma unroll
            for (int j = 0; j < 4; j++) {
                int col = warp_n * 32 + j * 8 + g;
                bfr[j][0] = __float_as_uint(Bs[kk + tig][col]);
                bfr[j][1] = __float_as_uint(Bs[kk + tig + 4][col]);
            }
#pragma unroll
            for (int i = 0; i < 4; i++)
#pragma unroll
                for (int j = 0; j < 4; j++) mma_tf32(acc[i][j], afr[i], bfr[j]);
        }
    }

#pragma unroll
    for (int i = 0; i < 4; i++) {
        int r = m0 + warp_m * 64 + i * 16 + g;
#pragma unroll
        for (int j = 0; j < 4; j++) {
            int n = n0 + warp_n * 32 + j * 8 + tig * 2;
            float bf0 = bfc[n], bf1 = bfc[n + 1];
            *(float2*)&C[(size_t)r * VOCABX + n] =
                make_float2(acc[i][j][0] + bf0, acc[i][j][1] + bf1);
            *(float2*)&C[(size_t)(r + 8) * VOCABX + n] =
                make_float2(acc[i][j][2] + bf0, acc[i][j][3] + bf1);
        }
    }
}

// ---------------- launcher ----------------
extern "C" void kernel_launch(void* const* d_in, const int* in_sizes, int n_in,
                              void* d_out, int out_size) {
    const int*   x      = (const int*)d_in[0];
    const float* hidden = (const float*)d_in[1];
    const float* enc    = (const float*)d_in[2];
    const float* E      = (const float*)d_in[3];
    const float* W1     = (const float*)d_in[4];
    const float* b1     = (const float*)d_in[5];
    const float* W2     = (const float*)d_in[6];
    const float* b2     = (const float*)d_in[7];
    const float* V      = (const float*)d_in[8];
    // d_in[9]  = bv     (dropped: softmax shift-invariant)
    const float* Wx     = (const float*)d_in[10];
    // d_in[11] = Wh     (dead in reference)
    const float* b_gru  = (const float*)d_in[12];
    const float* Wfc    = (const float*)d_in[13];
    const float* bfc    = (const float*)d_in[14];

    float* out        = (float*)d_out;
    float* out_logits = out;                                  // B*VOCAB
    float* out_state  = out + (size_t)Bx * VOCABX;            // B*U
    float* out_attn   = out + (size_t)Bx * VOCABX + Bx * UX;  // B*T

    k_zero_S<<<(Bx * Tx + 255) / 256, 256>>>();
    k_hw2<<<dim3(UX / 64, Bx / 64), 256>>>(hidden, W2, b1, b2);
    k_score_tc<<<dim3(UX / 128, Bx), 256>>>(enc, W1, V);
    k_softmax<<<Bx, 128>>>(x, E, out_attn);
    k_ctx<<<dim3(Bx, ENCX / 256), 256>>>(enc);
    k_gate<<<dim3(GXN / 64, Bx / 64), 256>>>(Wx, b_gru);
    k_state<<<(Bx * UX + 255) / 256, 256>>>(out_state);
    k_logits_tc<<<dim3(VOCABX / 128, Bx / 128), 256>>>(out_state, Wfc, bfc, out_logits);
}